// round 8
// baseline (speedup 1.0000x reference)
#include <cuda_runtime.h>
#include <cuda_bf16.h>
#include <math.h>
#include <stdint.h>

namespace {
constexpr int kS = 2048;
constexpr int kB = 32;
constexpr int kD = 256;
constexpr int kH = 4;
constexpr int kN = kS * kB;
constexpr float kEps = 1e-5f;
// Stage: Ahi 16K | Alo 16K | Bhi 8K | Blo 8K = 48K, double-buffered = 96K
constexpr int kStg = 49152;
constexpr int kOffAlo = 16384;
constexpr int kOffBhi = 32768;
constexpr int kOffBlo = 40960;
constexpr int kSmemTotal = 2 * kStg;
}  // namespace

__device__ float g_bufq[2][(size_t)kN * kD];
__device__ float g_bufk[2][(size_t)kN * kD];
__device__ float g_bufv[2][(size_t)kN * kD];
__device__ float g_t2[(size_t)kN * kD];
__device__ float g_s1a[kD], g_s2a[kD], g_s1b[kD], g_s2b[kD];
__device__ float g_scA[kD], g_shA[kD], g_scB[kD], g_shB[kD];
__device__ float g_se[kB * kD], g_wv[kB * kD];
__device__ float g_concat[kB * kH * kD];
__device__ __nv_bfloat16 g_whi[20][kD * kD];
__device__ __nv_bfloat16 g_wlo[20][kD * kD];

__device__ __forceinline__ uint32_t smem_u32(const void* p) {
    uint32_t a;
    asm("{ .reg .u64 t; cvta.to.shared.u64 t, %1; cvt.u32.u64 %0, t; }"
        : "=r"(a) : "l"(p));
    return a;
}
__device__ __forceinline__ void cp16(uint32_t dst, const void* src) {
    asm volatile("cp.async.cg.shared.global [%0], [%1], 16;" :: "r"(dst), "l"(src));
}
#define CP_COMMIT() asm volatile("cp.async.commit_group;" ::: "memory")
#define CP_WAIT0()  asm volatile("cp.async.wait_group 0;" ::: "memory")

__device__ __forceinline__ void ldmx4(uint32_t* r, uint32_t addr) {
    asm volatile("ldmatrix.sync.aligned.m8n8.x4.shared.b16 {%0,%1,%2,%3}, [%4];"
                 : "=r"(r[0]), "=r"(r[1]), "=r"(r[2]), "=r"(r[3]) : "r"(addr));
}
__device__ __forceinline__ void mma16816(float* d, const uint32_t* a,
                                         uint32_t b0, uint32_t b1) {
    asm volatile(
        "mma.sync.aligned.m16n8k16.row.col.f32.bf16.bf16.f32 "
        "{%0,%1,%2,%3}, {%4,%5,%6,%7}, {%8,%9}, {%0,%1,%2,%3};"
        : "+f"(d[0]), "+f"(d[1]), "+f"(d[2]), "+f"(d[3])
        : "r"(a[0]), "r"(a[1]), "r"(a[2]), "r"(a[3]), "r"(b0), "r"(b1));
}

// Weight image: per row n, per 64-k chunk, 8 granules of 16B XOR-swizzled by n&7.
__global__ void preconvert_w(const float* __restrict__ wq, const float* __restrict__ wk,
                             const float* __restrict__ wv, const float* __restrict__ wl1,
                             const float* __restrict__ wl2) {
    const int g = blockIdx.x;
    const int slot = g >> 2, head = g & 3;
    const float* src;
    switch (slot) {
        case 0: src = wq; break;
        case 1: src = wk; break;
        case 2: src = wv; break;
        case 3: src = wl1; break;
        default: src = wl2; break;
    }
    src += (size_t)head * kD * kD;
    const int idx = blockIdx.y * 256 + threadIdx.x;
    const int n = idx >> 4;
    const int k0 = (idx & 15) * 16;
#pragma unroll
    for (int j = 0; j < 16; ++j) {
        const int k = k0 + j;
        const float x = src[n * kD + k];
        const __nv_bfloat16 h = __float2bfloat16(x);
        const __nv_bfloat16 l = __float2bfloat16(x - __bfloat162float(h));
        const int gg = (k >> 3) & 7;
        const int kpos = (k & ~63) | ((gg ^ (n & 7)) << 3) | (k & 7);
        g_whi[g][n * kD + kpos] = h;
        g_wlo[g][n * kD + kpos] = l;
    }
}

// ---------------------------------------------------------------------------
// GEMM + fused epilogues. CTA tile 128x64, grid (4, 512), 8 warps (2x4),
// warp tile 64x16. bf16 hi/lo 3-term split, 2 CTAs/SM.
// MODE: 0 plain; 1 relu((A-A2)*sc+sh); 2 relu(A*sc+sh)
// EPI : 0 store; 1 store+stats(C-aux); 2 store+stats(C);
//       3 no store, softmax accum: st1+=exp, st2+=exp*aux
// ---------------------------------------------------------------------------
template <int MODE, int EPI>
__global__ void __launch_bounds__(256, 2)
gemm_u(const float* __restrict__ A, const float* __restrict__ A2,
       const float* __restrict__ sc, const float* __restrict__ sh,
       const __nv_bfloat16* __restrict__ Whi, const __nv_bfloat16* __restrict__ Wlo,
       const float* __restrict__ bias, float* __restrict__ C,
       const float* __restrict__ aux, float* __restrict__ st1,
       float* __restrict__ st2) {
    extern __shared__ __align__(1024) char smem[];
    const int tid = threadIdx.x;
    const int lane = tid & 31, warp = tid >> 5;
    const int wm = warp >> 2, wn = warp & 3;
    const int n0 = blockIdx.x * 64;
    const int m0 = blockIdx.y * 128;

    float acc[4][2][4];
#pragma unroll
    for (int i = 0; i < 4; ++i)
#pragma unroll
        for (int j = 0; j < 2; ++j)
#pragma unroll
            for (int e = 0; e < 4; ++e) acc[i][j][e] = 0.f;

    const int ar = tid >> 1, ahalf = tid & 1;
    float va[32];

    auto ldgA = [&](int c) {
        const size_t base = (size_t)(m0 + ar) * kD + c * 64 + ahalf * 32;
        float4 t[8];
#pragma unroll
        for (int j = 0; j < 8; ++j) t[j] = *(const float4*)(A + base + j * 4);
        if (MODE == 1) {
#pragma unroll
            for (int j = 0; j < 8; ++j) {
                const float4 q = *(const float4*)(A2 + base + j * 4);
                t[j].x -= q.x; t[j].y -= q.y; t[j].z -= q.z; t[j].w -= q.w;
            }
        }
        if (MODE != 0) {
            const int kb = c * 64 + ahalf * 32;
#pragma unroll
            for (int j = 0; j < 8; ++j) {
                const float4 s4 = *(const float4*)(sc + kb + j * 4);
                const float4 h4 = *(const float4*)(sh + kb + j * 4);
                t[j].x = fmaxf(t[j].x * s4.x + h4.x, 0.f);
                t[j].y = fmaxf(t[j].y * s4.y + h4.y, 0.f);
                t[j].z = fmaxf(t[j].z * s4.z + h4.z, 0.f);
                t[j].w = fmaxf(t[j].w * s4.w + h4.w, 0.f);
            }
        }
#pragma unroll
        for (int j = 0; j < 8; ++j) {
            va[j * 4 + 0] = t[j].x; va[j * 4 + 1] = t[j].y;
            va[j * 4 + 2] = t[j].z; va[j * 4 + 3] = t[j].w;
        }
    };

    auto stsA = [&](int s) {
        char* ahp = smem + s * kStg;
        char* alp = ahp + kOffAlo;
#pragma unroll
        for (int jg = 0; jg < 4; ++jg) {
            union { __nv_bfloat16 h[8]; uint4 u; } H, L;
#pragma unroll
            for (int e = 0; e < 8; ++e) {
                const float v = va[jg * 8 + e];
                H.h[e] = __float2bfloat16(v);
                L.h[e] = __float2bfloat16(v - __bfloat162float(H.h[e]));
            }
            const int gg = ahalf * 4 + jg;
            const int off = ar * 128 + ((gg ^ (ar & 7)) << 4);
            *(uint4*)(ahp + off) = H.u;
            *(uint4*)(alp + off) = L.u;
        }
    };

    auto cpB = [&](int c, int s) {
        const int lv = tid >> 7;            // 0 = hi, 1 = lo
        const int r = (tid & 127) >> 1;     // row 0..63
        const int hf = tid & 1;             // 64B half
        const __nv_bfloat16* src =
            (lv ? Wlo : Whi) + (size_t)(n0 + r) * kD + c * 64 + hf * 32;
        const uint32_t dst = smem_u32(smem + s * kStg + kOffBhi) + lv * 8192 +
                             r * 128 + hf * 64;
#pragma unroll
        for (int g = 0; g < 4; ++g) cp16(dst + g * 16, src + g * 8);
    };

    const int lidx = lane >> 3, rowoff = lane & 7;
    const int mrow = (lidx & 1) * 8 + rowoff;
    const int halfbit = lidx >> 1;
    int rowA[4];
#pragma unroll
    for (int i = 0; i < 4; ++i) rowA[i] = (wm * 64 + i * 16 + mrow) * 128;
    const int rowB = (wn * 16 + mrow) * 128;

    auto compute = [&](int s) {
        const uint32_t aB = smem_u32(smem + s * kStg);
        const uint32_t bB = aB + kOffBhi;
#pragma unroll
        for (int ks = 0; ks < 4; ++ks) {
            const int gsw = (((ks << 1) + halfbit) ^ rowoff) << 4;
            uint32_t ah[4][4], bh[4], bl[4];
#pragma unroll
            for (int i = 0; i < 4; ++i) ldmx4(ah[i], aB + rowA[i] + gsw);
            ldmx4(bh, bB + rowB + gsw);
            ldmx4(bl, bB + 8192 + rowB + gsw);
#pragma unroll
            for (int i = 0; i < 4; ++i)
#pragma unroll
                for (int j = 0; j < 2; ++j)
                    mma16816(acc[i][j], ah[i], bh[j], bh[2 + j]);
#pragma unroll
            for (int i = 0; i < 4; ++i)
#pragma unroll
                for (int j = 0; j < 2; ++j)
                    mma16816(acc[i][j], ah[i], bl[j], bl[2 + j]);
#pragma unroll
            for (int i = 0; i < 4; ++i) ldmx4(ah[i], aB + kOffAlo + rowA[i] + gsw);
#pragma unroll
            for (int i = 0; i < 4; ++i)
#pragma unroll
                for (int j = 0; j < 2; ++j)
                    mma16816(acc[i][j], ah[i], bh[j], bh[2 + j]);
        }
    };

    ldgA(0);
    cpB(0, 0);
    CP_COMMIT();
    stsA(0);
#pragma unroll
    for (int c = 0; c < 4; ++c) {
        const int s = c & 1;
        CP_WAIT0();
        __syncthreads();
        if (c < 3) {
            ldgA(c + 1);
            cpB(c + 1, s ^ 1);
            CP_COMMIT();
        }
        compute(s);
        if (c < 3) stsA(s ^ 1);
    }

    // ---- epilogues ----
    const int er = lane >> 2, ec = (lane & 3) * 2;
    if (EPI == 3) {
        // softmax accumulation (bias constant over s: cancels, skip it)
#pragma unroll
        for (int i = 0; i < 2; ++i) {       // pair (i, i+2): same b
#pragma unroll
            for (int rh = 0; rh < 2; ++rh) {
                const int mr1 = m0 + wm * 64 + i * 16 + rh * 8 + er;
                const int mr2 = mr1 + 32;
                const int b = mr1 & 31;
#pragma unroll
                for (int j = 0; j < 2; ++j) {
                    const int nc = n0 + wn * 16 + j * 8 + ec;
                    const float e1x = __expf(acc[i][j][rh * 2 + 0]);
                    const float e1y = __expf(acc[i][j][rh * 2 + 1]);
                    const float e2x = __expf(acc[i + 2][j][rh * 2 + 0]);
                    const float e2y = __expf(acc[i + 2][j][rh * 2 + 1]);
                    const float2 v1 = *(const float2*)(aux + (size_t)mr1 * kD + nc);
                    const float2 v2 = *(const float2*)(aux + (size_t)mr2 * kD + nc);
                    atomicAdd(&st1[b * kD + nc + 0], e1x + e2x);
                    atomicAdd(&st1[b * kD + nc + 1], e1y + e2y);
                    atomicAdd(&st2[b * kD + nc + 0], e1x * v1.x + e2x * v2.x);
                    atomicAdd(&st2[b * kD + nc + 1], e1y * v1.y + e2y * v2.y);
                }
            }
        }
    } else {
        float s1l[4] = {0.f, 0.f, 0.f, 0.f}, s2l[4] = {0.f, 0.f, 0.f, 0.f};
#pragma unroll
        for (int i = 0; i < 4; ++i) {
            const int mr = m0 + wm * 64 + i * 16 + er;
#pragma unroll
            for (int j = 0; j < 2; ++j) {
                const int nc = n0 + wn * 16 + j * 8 + ec;
                const float2 b2 = *(const float2*)(bias + nc);
                float2 o0, o1;
                o0.x = acc[i][j][0] + b2.x; o0.y = acc[i][j][1] + b2.y;
                o1.x = acc[i][j][2] + b2.x; o1.y = acc[i][j][3] + b2.y;
                *(float2*)(C + (size_t)mr * kD + nc) = o0;
                *(float2*)(C + (size_t)(mr + 8) * kD + nc) = o1;
                if (EPI != 0) {
                    float x0 = o0.x, x1 = o0.y, x2 = o1.x, x3 = o1.y;
                    if (EPI == 1) {
                        const float2 q0 = *(const float2*)(aux + (size_t)mr * kD + nc);
                        const float2 q1 = *(const float2*)(aux + (size_t)(mr + 8) * kD + nc);
                        x0 -= q0.x; x1 -= q0.y; x2 -= q1.x; x3 -= q1.y;
                    }
                    s1l[j * 2 + 0] += x0 + x2;
                    s1l[j * 2 + 1] += x1 + x3;
                    s2l[j * 2 + 0] += x0 * x0 + x2 * x2;
                    s2l[j * 2 + 1] += x1 * x1 + x3 * x3;
                }
            }
        }
        if (EPI != 0) {
#pragma unroll
            for (int off = 4; off < 32; off <<= 1) {
#pragma unroll
                for (int t = 0; t < 4; ++t) {
                    s1l[t] += __shfl_xor_sync(0xffffffffu, s1l[t], off);
                    s2l[t] += __shfl_xor_sync(0xffffffffu, s2l[t], off);
                }
            }
            if (lane < 4) {
#pragma unroll
                for (int t = 0; t < 4; ++t) {
                    const int nc = n0 + wn * 16 + (t >> 1) * 8 + lane * 2 + (t & 1);
                    atomicAdd(&st1[nc], s1l[t]);
                    atomicAdd(&st2[nc], s2l[t]);
                }
            }
        }
    }
}

__global__ void bn_finalize_kernel(const float* __restrict__ s1,
                                   const float* __restrict__ s2,
                                   const float* __restrict__ gamma,
                                   const float* __restrict__ beta,
                                   float* __restrict__ scale,
                                   float* __restrict__ shift) {
    const int d = threadIdx.x;
    const double mean = (double)s1[d] / (double)kN;
    const double var = (double)s2[d] / (double)kN - mean * mean;
    const float rs = (float)rsqrt(var + (double)kEps);
    const float scv = rs * gamma[d];
    scale[d] = scv;
    shift[d] = beta[d] - (float)mean * scv;
}

__global__ void zero_kernel(float* s1a, float* s2a, float* s1b, float* s2b,
                            float* se, float* wv) {
    const int g = blockIdx.x * blockDim.x + threadIdx.x;
    se[g] = 0.f;
    wv[g] = 0.f;
    if (g < kD) { s1a[g] = 0.f; s2a[g] = 0.f; s1b[g] = 0.f; s2b[g] = 0.f; }
}

__global__ void softmax_final_kernel(const float* __restrict__ se,
                                     const float* __restrict__ wv,
                                     float* __restrict__ concat, int head) {
    const int b = blockIdx.x;
    const int d = threadIdx.x;
    concat[b * (kH * kD) + head * kD + d] = wv[b * kD + d] / se[b * kD + d];
}

__global__ void __launch_bounds__(256)
mlp_kernel(const float* __restrict__ concat,
           const float* __restrict__ mw0, const float* __restrict__ mb0,
           const float* __restrict__ mw1, const float* __restrict__ mb1,
           const float* __restrict__ mw2, const float* __restrict__ mb2,
           float* __restrict__ out) {
    __shared__ float xs[kH * kD];
    __shared__ float h0[kD];
    __shared__ float h1[kD];
    const int b = blockIdx.x;
    const int j = threadIdx.x;
    for (int t = j; t < kH * kD; t += kD) xs[t] = concat[b * kH * kD + t];
    __syncthreads();
    float acc = mb0[j];
    for (int t = 0; t < kH * kD; t++) acc += xs[t] * mw0[(size_t)j * (kH * kD) + t];
    h0[j] = fmaxf(acc, 0.f);
    __syncthreads();
    acc = mb1[j];
    for (int t = 0; t < kD; t++) acc += h0[t] * mw1[(size_t)j * kD + t];
    h1[j] = fmaxf(acc, 0.f);
    __syncthreads();
    acc = mb2[j];
    for (int t = 0; t < kD; t++) acc += h1[t] * mw2[(size_t)j * kD + t];
    out[b * kD + j] = acc;
}

extern "C" void kernel_launch(void* const* d_in, const int* in_sizes, int n_in,
                              void* d_out, int out_size) {
    (void)in_sizes; (void)n_in; (void)out_size;
    const float* in_q  = (const float*)d_in[0];
    const float* in_k  = (const float*)d_in[1];
    const float* in_v  = (const float*)d_in[2];
    const float* wq    = (const float*)d_in[3];
    const float* bqv   = (const float*)d_in[4];
    const float* wk    = (const float*)d_in[5];
    const float* bkv   = (const float*)d_in[6];
    const float* wvw   = (const float*)d_in[7];
    const float* bvv   = (const float*)d_in[8];
    const float* g1    = (const float*)d_in[9];
    const float* be1   = (const float*)d_in[10];
    const float* wl1   = (const float*)d_in[11];
    const float* bl1   = (const float*)d_in[12];
    const float* g2    = (const float*)d_in[13];
    const float* be2   = (const float*)d_in[14];
    const float* wl2   = (const float*)d_in[15];
    const float* bl2   = (const float*)d_in[16];
    const float* mw0   = (const float*)d_in[17];
    const float* mb0   = (const float*)d_in[18];
    const float* mw1   = (const float*)d_in[19];
    const float* mb1   = (const float*)d_in[20];
    const float* mw2   = (const float*)d_in[21];
    const float* mb2   = (const float*)d_in[22];

    float *bq, *bk, *bv, *t2, *scA, *shA, *scB, *shB, *se, *wv, *concat;
    float *s1a, *s2a, *s1b, *s2b;
    __nv_bfloat16 *whi, *wlo;
    cudaGetSymbolAddress((void**)&bq, g_bufq);
    cudaGetSymbolAddress((void**)&bk, g_bufk);
    cudaGetSymbolAddress((void**)&bv, g_bufv);
    cudaGetSymbolAddress((void**)&t2, g_t2);
    cudaGetSymbolAddress((void**)&s1a, g_s1a);
    cudaGetSymbolAddress((void**)&s2a, g_s2a);
    cudaGetSymbolAddress((void**)&s1b, g_s1b);
    cudaGetSymbolAddress((void**)&s2b, g_s2b);
    cudaGetSymbolAddress((void**)&scA, g_scA);
    cudaGetSymbolAddress((void**)&shA, g_shA);
    cudaGetSymbolAddress((void**)&scB, g_scB);
    cudaGetSymbolAddress((void**)&shB, g_shB);
    cudaGetSymbolAddress((void**)&se, g_se);
    cudaGetSymbolAddress((void**)&wv, g_wv);
    cudaGetSymbolAddress((void**)&concat, g_concat);
    cudaGetSymbolAddress((void**)&whi, g_whi);
    cudaGetSymbolAddress((void**)&wlo, g_wlo);

    cudaFuncSetAttribute(gemm_u<0,0>, cudaFuncAttributeMaxDynamicSharedMemorySize, kSmemTotal);
    cudaFuncSetAttribute(gemm_u<0,1>, cudaFuncAttributeMaxDynamicSharedMemorySize, kSmemTotal);
    cudaFuncSetAttribute(gemm_u<1,2>, cudaFuncAttributeMaxDynamicSharedMemorySize, kSmemTotal);
    cudaFuncSetAttribute(gemm_u<2,3>, cudaFuncAttributeMaxDynamicSharedMemorySize, kSmemTotal);

    preconvert_w<<<dim3(20, 16), 256>>>(wq, wk, wvw, wl1, wl2);

    const size_t bufElems = (size_t)kN * kD;
    const dim3 gg(kD / 64, kN / 128);  // (4, 512)

    auto WH = [&](int slot, int head) { return whi + (size_t)(slot * 4 + head) * kD * kD; };
    auto WL = [&](int slot, int head) { return wlo + (size_t)(slot * 4 + head) * kD * kD; };

    const float *qin = in_q, *kin = in_k, *vin = in_v;
    for (int i = 0; i < kH; i++) {
        float* qout = bq + (size_t)(i & 1) * bufElems;
        float* kout = bk + (size_t)(i & 1) * bufElems;
        float* vout = bv + (size_t)(i & 1) * bufElems;

        zero_kernel<<<32, 256>>>(s1a, s2a, s1b, s2b, se, wv);

        gemm_u<0,0><<<gg, 256, kSmemTotal>>>(qin, nullptr, nullptr, nullptr,
            WH(0,i), WL(0,i), bqv + i*kD, qout, nullptr, nullptr, nullptr);
        gemm_u<0,0><<<gg, 256, kSmemTotal>>>(vin, nullptr, nullptr, nullptr,
            WH(2,i), WL(2,i), bvv + i*kD, vout, nullptr, nullptr, nullptr);
        // k projection + fused BN1 stats of (k' - q')
        gemm_u<0,1><<<gg, 256, kSmemTotal>>>(kin, nullptr, nullptr, nullptr,
            WH(1,i), WL(1,i), bkv + i*kD, kout, qout, s1a, s2a);

        bn_finalize_kernel<<<1, 256>>>(s1a, s2a, g1 + i*kD, be1 + i*kD, scA, shA);

        // linear1 on relu(bn(k'-q')) + fused BN2 stats of its output
        gemm_u<1,2><<<gg, 256, kSmemTotal>>>(kout, qout, scA, shA,
            WH(3,i), WL(3,i), bl1 + i*kD, t2, nullptr, s1b, s2b);

        bn_finalize_kernel<<<1, 256>>>(s1b, s2b, g2 + i*kD, be2 + i*kD, scB, shB);

        // linear2 + fused softmax accumulation against v'
        gemm_u<2,3><<<gg, 256, kSmemTotal>>>(t2, nullptr, scB, shB,
            WH(4,i), WL(4,i), bl2 + i*kD, nullptr, vout, se, wv);

        softmax_final_kernel<<<kB, 256>>>(se, wv, concat, i);

        qin = qout; kin = kout; vin = vout;
    }

    mlp_kernel<<<kB, 256>>>(concat, mw0, mb0, mw1, mb1, mw2, mb2, (float*)d_out);
}

// round 9
// speedup vs baseline: 1.3209x; 1.3209x over previous
#include <cuda_runtime.h>
#include <cuda_bf16.h>
#include <math.h>
#include <stdint.h>

namespace {
constexpr int kS = 2048;
constexpr int kB = 32;
constexpr int kD = 256;
constexpr int kH = 4;
constexpr int kN = kS * kB;
constexpr float kEps = 1e-5f;
// Stage: A 16K (128 rows x 128B packed hi|lo) + B 16K = 32K, double = 64K
constexpr int kStg = 32768;
constexpr int kOffB = 16384;
constexpr int kSmemTotal = 2 * kStg;
}  // namespace

__device__ float g_bufq[2][(size_t)kN * kD];
__device__ float g_bufk[2][(size_t)kN * kD];
__device__ float g_bufv[2][(size_t)kN * kD];
__device__ float g_t2[(size_t)kN * kD];
__device__ float g_s1a[kD], g_s2a[kD], g_s1b[kD], g_s2b[kD];
__device__ float g_scA[kD], g_shA[kD], g_scB[kD], g_shB[kD];
__device__ float g_se[kB * kD], g_wv[kB * kD];
__device__ float g_concat[kB * kH * kD];
// Weight image: [matrix][chunk c<8][n<256][128B row: hi gran 0-3 | lo gran 4-7,
// granule u stored at byte ((u ^ (n&7))<<4)]. 256KB per matrix.
__device__ unsigned char g_wimg[20 * 262144];

__device__ __forceinline__ uint32_t smem_u32(const void* p) {
    uint32_t a;
    asm("{ .reg .u64 t; cvta.to.shared.u64 t, %1; cvt.u32.u64 %0, t; }"
        : "=r"(a) : "l"(p));
    return a;
}
__device__ __forceinline__ void cp16(uint32_t dst, const void* src) {
    asm volatile("cp.async.cg.shared.global [%0], [%1], 16;" :: "r"(dst), "l"(src));
}
#define CP_COMMIT() asm volatile("cp.async.commit_group;" ::: "memory")
#define CP_WAIT0()  asm volatile("cp.async.wait_group 0;" ::: "memory")

__device__ __forceinline__ void ldmx4(uint32_t* r, uint32_t addr) {
    asm volatile("ldmatrix.sync.aligned.m8n8.x4.shared.b16 {%0,%1,%2,%3}, [%4];"
                 : "=r"(r[0]), "=r"(r[1]), "=r"(r[2]), "=r"(r[3]) : "r"(addr));
}
__device__ __forceinline__ void mma16816(float* d, const uint32_t* a,
                                         uint32_t b0, uint32_t b1) {
    asm volatile(
        "mma.sync.aligned.m16n8k16.row.col.f32.bf16.bf16.f32 "
        "{%0,%1,%2,%3}, {%4,%5,%6,%7}, {%8,%9}, {%0,%1,%2,%3};"
        : "+f"(d[0]), "+f"(d[1]), "+f"(d[2]), "+f"(d[3])
        : "r"(a[0]), "r"(a[1]), "r"(a[2]), "r"(a[3]), "r"(b0), "r"(b1));
}

__global__ void preconvert_w(const float* __restrict__ wq, const float* __restrict__ wk,
                             const float* __restrict__ wv, const float* __restrict__ wl1,
                             const float* __restrict__ wl2) {
    const int g = blockIdx.x;
    const int slot = g >> 2, head = g & 3;
    const float* src;
    switch (slot) {
        case 0: src = wq; break;
        case 1: src = wk; break;
        case 2: src = wv; break;
        case 3: src = wl1; break;
        default: src = wl2; break;
    }
    src += (size_t)head * kD * kD;
    unsigned char* img = g_wimg + (size_t)g * 262144;
    const int idx = blockIdx.y * 256 + threadIdx.x;  // grid.y=16 -> 0..4095
    const int n = idx >> 4;
    const int k0 = (idx & 15) * 16;
    const int nx = n & 7;
#pragma unroll
    for (int j = 0; j < 16; ++j) {
        const int k = k0 + j;
        const float x = src[n * kD + k];
        const __nv_bfloat16 h = __float2bfloat16(x);
        const __nv_bfloat16 l = __float2bfloat16(x - __bfloat162float(h));
        const int c = k >> 5, kl = k & 31;
        const int u = kl >> 3, e2 = (kl & 7) * 2;
        unsigned char* row = img + ((size_t)(c * 256 + n) << 7);
        *(__nv_bfloat16*)(row + ((u ^ nx) << 4) + e2) = h;
        *(__nv_bfloat16*)(row + (((u + 4) ^ nx) << 4) + e2) = l;
    }
}

// ---------------------------------------------------------------------------
// GEMM + fused epilogues. CTA tile 128x128, K in 8 chunks of 32.
// Grid (2, 512), 256 threads (8 warps, 2m x 4n), warp tile 64x32. 2 CTAs/SM.
// bf16 hi/lo 3-term split (Ah*Bh + Ah*Bl + Al*Bh), fp32 accum.
// MODE: 0 plain; 1 relu((A-A2)*sc+sh); 2 relu(A*sc+sh)
// EPI : 0 store; 1 store+col-stats(C-aux); 2 store+col-stats(C);
//       3 no store: smem-reduced softmax accum st1+=exp, st2+=exp*aux
// ---------------------------------------------------------------------------
template <int MODE, int EPI>
__global__ void __launch_bounds__(256, 2)
gemm_u(const float* __restrict__ A, const float* __restrict__ A2,
       const float* __restrict__ sc, const float* __restrict__ sh,
       const unsigned char* __restrict__ Wimg, const float* __restrict__ bias,
       float* __restrict__ C, const float* __restrict__ aux,
       float* __restrict__ st1, float* __restrict__ st2) {
    extern __shared__ __align__(1024) char smem[];
    const uint32_t sb = smem_u32(smem);
    const int tid = threadIdx.x;
    const int lane = tid & 31, warp = tid >> 5;
    const int wm = warp >> 2, wn = warp & 3;
    const int n0 = blockIdx.x * 128;
    const int m0 = blockIdx.y * 128;

    float acc[4][4][4];
#pragma unroll
    for (int i = 0; i < 4; ++i)
#pragma unroll
        for (int j = 0; j < 4; ++j)
#pragma unroll
            for (int e = 0; e < 4; ++e) acc[i][j][e] = 0.f;

    const int ar = tid >> 1, ahalf = tid & 1, arx = ar & 7;
    float va[16];

    auto ldgA = [&](int c) {
        const size_t base = (size_t)(m0 + ar) * kD + c * 32 + ahalf * 16;
        float4 t[4];
#pragma unroll
        for (int j = 0; j < 4; ++j) t[j] = *(const float4*)(A + base + j * 4);
        if (MODE == 1) {
#pragma unroll
            for (int j = 0; j < 4; ++j) {
                const float4 q = *(const float4*)(A2 + base + j * 4);
                t[j].x -= q.x; t[j].y -= q.y; t[j].z -= q.z; t[j].w -= q.w;
            }
        }
        if (MODE != 0) {
            const int kb = c * 32 + ahalf * 16;
#pragma unroll
            for (int j = 0; j < 4; ++j) {
                const float4 s4 = *(const float4*)(sc + kb + j * 4);
                const float4 h4 = *(const float4*)(sh + kb + j * 4);
                t[j].x = fmaxf(t[j].x * s4.x + h4.x, 0.f);
                t[j].y = fmaxf(t[j].y * s4.y + h4.y, 0.f);
                t[j].z = fmaxf(t[j].z * s4.z + h4.z, 0.f);
                t[j].w = fmaxf(t[j].w * s4.w + h4.w, 0.f);
            }
        }
#pragma unroll
        for (int j = 0; j < 4; ++j) {
            va[j * 4 + 0] = t[j].x; va[j * 4 + 1] = t[j].y;
            va[j * 4 + 2] = t[j].z; va[j * 4 + 3] = t[j].w;
        }
    };

    auto stsA = [&](int s) {
        char* ap = smem + s * kStg + ar * 128;
#pragma unroll
        for (int q = 0; q < 2; ++q) {
            union { __nv_bfloat16 h[8]; uint4 u; } H, L;
#pragma unroll
            for (int e = 0; e < 8; ++e) {
                const float v = va[q * 8 + e];
                H.h[e] = __float2bfloat16(v);
                L.h[e] = __float2bfloat16(v - __bfloat162float(H.h[e]));
            }
            const int u = ahalf * 2 + q;
            *(uint4*)(ap + ((u ^ arx) << 4)) = H.u;
            *(uint4*)(ap + (((u + 4) ^ arx) << 4)) = L.u;
        }
    };

    auto cpB = [&](int c, int s) {
        const int r = tid >> 1, hf = tid & 1;
        const unsigned char* src = Wimg + (((size_t)(c * 256 + n0 + r)) << 7) + hf * 64;
        const uint32_t dst = sb + s * kStg + kOffB + r * 128 + hf * 64;
#pragma unroll
        for (int g = 0; g < 4; ++g) cp16(dst + g * 16, src + g * 16);
    };

    const int lidx = lane >> 3, rowoff = lane & 7;
    const int mrow = (lidx & 1) * 8 + rowoff;
    const int halfbit = lidx >> 1;
    int rowA[4], rowB[2];
#pragma unroll
    for (int i = 0; i < 4; ++i) rowA[i] = (wm * 64 + i * 16 + mrow) * 128;
#pragma unroll
    for (int j = 0; j < 2; ++j) rowB[j] = (wn * 32 + j * 16 + mrow) * 128;

    auto compute = [&](int s) {
        const uint32_t aB = sb + s * kStg;
        const uint32_t bB = aB + kOffB;
#pragma unroll
        for (int ks = 0; ks < 2; ++ks) {
            const int uh = ks * 2 + halfbit;
            const int posH = ((uh ^ rowoff) << 4);
            const int posL = (((uh + 4) ^ rowoff) << 4);
            uint32_t ah[4][4], bh[2][4], bl[2][4];
#pragma unroll
            for (int i = 0; i < 4; ++i) ldmx4(ah[i], aB + rowA[i] + posH);
#pragma unroll
            for (int j = 0; j < 2; ++j) ldmx4(bh[j], bB + rowB[j] + posH);
#pragma unroll
            for (int j = 0; j < 2; ++j) ldmx4(bl[j], bB + rowB[j] + posL);
#pragma unroll
            for (int i = 0; i < 4; ++i)
#pragma unroll
                for (int j = 0; j < 4; ++j)
                    mma16816(acc[i][j], ah[i], bh[j >> 1][j & 1], bh[j >> 1][2 + (j & 1)]);
#pragma unroll
            for (int i = 0; i < 4; ++i)
#pragma unroll
                for (int j = 0; j < 4; ++j)
                    mma16816(acc[i][j], ah[i], bl[j >> 1][j & 1], bl[j >> 1][2 + (j & 1)]);
#pragma unroll
            for (int i = 0; i < 4; ++i) ldmx4(ah[i], aB + rowA[i] + posL);
#pragma unroll
            for (int i = 0; i < 4; ++i)
#pragma unroll
                for (int j = 0; j < 4; ++j)
                    mma16816(acc[i][j], ah[i], bh[j >> 1][j & 1], bh[j >> 1][2 + (j & 1)]);
        }
    };

    ldgA(0);
    cpB(0, 0);
    CP_COMMIT();
    stsA(0);
#pragma unroll 1
    for (int c = 0; c < 8; ++c) {
        const int s = c & 1;
        CP_WAIT0();
        __syncthreads();
        if (c < 7) {
            ldgA(c + 1);
            cpB(c + 1, s ^ 1);
            CP_COMMIT();
        }
        compute(s);
        if (c < 7) stsA(s ^ 1);
    }

    // ---- epilogues ----
    const int er = lane >> 2, ec = (lane & 3) * 2;
    if (EPI == 3) {
        __syncthreads();  // done with stage smem; reuse for reduction
        float* se_s = (float*)smem;          // [32][128]
        float* wv_s = se_s + 4096;           // [32][128]
        for (int t = tid; t < 8192; t += 256) se_s[t] = 0.f;
        __syncthreads();
#pragma unroll
        for (int i = 0; i < 4; ++i) {
            const int mr = m0 + wm * 64 + i * 16 + er;
#pragma unroll
            for (int j = 0; j < 4; ++j) {
                const int ncl = wn * 32 + j * 8 + ec;
                const float2 v0 = *(const float2*)(aux + (size_t)mr * kD + n0 + ncl);
                const float2 v1 = *(const float2*)(aux + (size_t)(mr + 8) * kD + n0 + ncl);
                const float e0 = __expf(acc[i][j][0]);
                const float e1 = __expf(acc[i][j][1]);
                const float e2 = __expf(acc[i][j][2]);
                const float e3 = __expf(acc[i][j][3]);
                const int b0 = (mr & 31) * 128 + ncl;
                const int b1 = ((mr + 8) & 31) * 128 + ncl;
                atomicAdd(&se_s[b0 + 0], e0);
                atomicAdd(&se_s[b0 + 1], e1);
                atomicAdd(&se_s[b1 + 0], e2);
                atomicAdd(&se_s[b1 + 1], e3);
                atomicAdd(&wv_s[b0 + 0], e0 * v0.x);
                atomicAdd(&wv_s[b0 + 1], e1 * v0.y);
                atomicAdd(&wv_s[b1 + 0], e2 * v1.x);
                atomicAdd(&wv_s[b1 + 1], e3 * v1.y);
            }
        }
        __syncthreads();
        for (int t = tid; t < 4096; t += 256) {
            const int b = t >> 7, ncl = t & 127;
            atomicAdd(&st1[b * kD + n0 + ncl], se_s[t]);
            atomicAdd(&st2[b * kD + n0 + ncl], wv_s[t]);
        }
    } else {
        float s1l[8], s2l[8];
#pragma unroll
        for (int t = 0; t < 8; ++t) { s1l[t] = 0.f; s2l[t] = 0.f; }
#pragma unroll
        for (int i = 0; i < 4; ++i) {
            const int mr = m0 + wm * 64 + i * 16 + er;
#pragma unroll
            for (int j = 0; j < 4; ++j) {
                const int nc = n0 + wn * 32 + j * 8 + ec;
                const float2 b2 = *(const float2*)(bias + nc);
                float2 o0, o1;
                o0.x = acc[i][j][0] + b2.x; o0.y = acc[i][j][1] + b2.y;
                o1.x = acc[i][j][2] + b2.x; o1.y = acc[i][j][3] + b2.y;
                *(float2*)(C + (size_t)mr * kD + nc) = o0;
                *(float2*)(C + (size_t)(mr + 8) * kD + nc) = o1;
                if (EPI != 0) {
                    float x0 = o0.x, x1 = o0.y, x2 = o1.x, x3 = o1.y;
                    if (EPI == 1) {
                        const float2 q0 = *(const float2*)(aux + (size_t)mr * kD + nc);
                        const float2 q1 = *(const float2*)(aux + (size_t)(mr + 8) * kD + nc);
                        x0 -= q0.x; x1 -= q0.y; x2 -= q1.x; x3 -= q1.y;
                    }
                    s1l[j * 2 + 0] += x0 + x2;
                    s1l[j * 2 + 1] += x1 + x3;
                    s2l[j * 2 + 0] += x0 * x0 + x2 * x2;
                    s2l[j * 2 + 1] += x1 * x1 + x3 * x3;
                }
            }
        }
        if (EPI != 0) {
#pragma unroll
            for (int off = 4; off < 32; off <<= 1) {
#pragma unroll
                for (int t = 0; t < 8; ++t) {
                    s1l[t] += __shfl_xor_sync(0xffffffffu, s1l[t], off);
                    s2l[t] += __shfl_xor_sync(0xffffffffu, s2l[t], off);
                }
            }
            if (lane < 4) {
#pragma unroll
                for (int t = 0; t < 8; ++t) {
                    const int nc = n0 + wn * 32 + (t >> 1) * 8 + lane * 2 + (t & 1);
                    atomicAdd(&st1[nc], s1l[t]);
                    atomicAdd(&st2[nc], s2l[t]);
                }
            }
        }
    }
}

__global__ void bn_finalize_kernel(const float* __restrict__ s1,
                                   const float* __restrict__ s2,
                                   const float* __restrict__ gamma,
                                   const float* __restrict__ beta,
                                   float* __restrict__ scale,
                                   float* __restrict__ shift) {
    const int d = threadIdx.x;
    const double mean = (double)s1[d] / (double)kN;
    const double var = (double)s2[d] / (double)kN - mean * mean;
    const float rs = (float)rsqrt(var + (double)kEps);
    const float scv = rs * gamma[d];
    scale[d] = scv;
    shift[d] = beta[d] - (float)mean * scv;
}

__global__ void zero_kernel(float* s1a, float* s2a, float* s1b, float* s2b,
                            float* se, float* wv) {
    const int g = blockIdx.x * blockDim.x + threadIdx.x;
    se[g] = 0.f;
    wv[g] = 0.f;
    if (g < kD) { s1a[g] = 0.f; s2a[g] = 0.f; s1b[g] = 0.f; s2b[g] = 0.f; }
}

__global__ void softmax_final_kernel(const float* __restrict__ se,
                                     const float* __restrict__ wv,
                                     float* __restrict__ concat, int head) {
    const int b = blockIdx.x;
    const int d = threadIdx.x;
    concat[b * (kH * kD) + head * kD + d] = wv[b * kD + d] / se[b * kD + d];
}

__global__ void __launch_bounds__(256)
mlp_kernel(const float* __restrict__ concat,
           const float* __restrict__ mw0, const float* __restrict__ mb0,
           const float* __restrict__ mw1, const float* __restrict__ mb1,
           const float* __restrict__ mw2, const float* __restrict__ mb2,
           float* __restrict__ out) {
    __shared__ float xs[kH * kD];
    __shared__ float h0[kD];
    __shared__ float h1[kD];
    const int b = blockIdx.x;
    const int j = threadIdx.x;
    for (int t = j; t < kH * kD; t += kD) xs[t] = concat[b * kH * kD + t];
    __syncthreads();
    float acc = mb0[j];
    for (int t = 0; t < kH * kD; t++) acc += xs[t] * mw0[(size_t)j * (kH * kD) + t];
    h0[j] = fmaxf(acc, 0.f);
    __syncthreads();
    acc = mb1[j];
    for (int t = 0; t < kD; t++) acc += h0[t] * mw1[(size_t)j * kD + t];
    h1[j] = fmaxf(acc, 0.f);
    __syncthreads();
    acc = mb2[j];
    for (int t = 0; t < kD; t++) acc += h1[t] * mw2[(size_t)j * kD + t];
    out[b * kD + j] = acc;
}

extern "C" void kernel_launch(void* const* d_in, const int* in_sizes, int n_in,
                              void* d_out, int out_size) {
    (void)in_sizes; (void)n_in; (void)out_size;
    const float* in_q  = (const float*)d_in[0];
    const float* in_k  = (const float*)d_in[1];
    const float* in_v  = (const float*)d_in[2];
    const float* wq    = (const float*)d_in[3];
    const float* bqv   = (const float*)d_in[4];
    const float* wk    = (const float*)d_in[5];
    const float* bkv   = (const float*)d_in[6];
    const float* wvw   = (const float*)d_in[7];
    const float* bvv   = (const float*)d_in[8];
    const float* g1    = (const float*)d_in[9];
    const float* be1   = (const float*)d_in[10];
    const float* wl1   = (const float*)d_in[11];
    const float* bl1   = (const float*)d_in[12];
    const float* g2    = (const float*)d_in[13];
    const float* be2   = (const float*)d_in[14];
    const float* wl2   = (const float*)d_in[15];
    const float* bl2   = (const float*)d_in[16];
    const float* mw0   = (const float*)d_in[17];
    const float* mb0   = (const float*)d_in[18];
    const float* mw1   = (const float*)d_in[19];
    const float* mb1   = (const float*)d_in[20];
    const float* mw2   = (const float*)d_in[21];
    const float* mb2   = (const float*)d_in[22];

    float *bq, *bk, *bv, *t2, *scA, *shA, *scB, *shB, *se, *wv, *concat;
    float *s1a, *s2a, *s1b, *s2b;
    unsigned char* wimg;
    cudaGetSymbolAddress((void**)&bq, g_bufq);
    cudaGetSymbolAddress((void**)&bk, g_bufk);
    cudaGetSymbolAddress((void**)&bv, g_bufv);
    cudaGetSymbolAddress((void**)&t2, g_t2);
    cudaGetSymbolAddress((void**)&s1a, g_s1a);
    cudaGetSymbolAddress((void**)&s2a, g_s2a);
    cudaGetSymbolAddress((void**)&s1b, g_s1b);
    cudaGetSymbolAddress((void**)&s2b, g_s2b);
    cudaGetSymbolAddress((void**)&scA, g_scA);
    cudaGetSymbolAddress((void**)&shA, g_shA);
    cudaGetSymbolAddress((void**)&scB, g_scB);
    cudaGetSymbolAddress((void**)&shB, g_shB);
    cudaGetSymbolAddress((void**)&se, g_se);
    cudaGetSymbolAddress((void**)&wv, g_wv);
    cudaGetSymbolAddress((void**)&concat, g_concat);
    cudaGetSymbolAddress((void**)&wimg, g_wimg);

    cudaFuncSetAttribute(gemm_u<0,0>, cudaFuncAttributeMaxDynamicSharedMemorySize, kSmemTotal);
    cudaFuncSetAttribute(gemm_u<0,1>, cudaFuncAttributeMaxDynamicSharedMemorySize, kSmemTotal);
    cudaFuncSetAttribute(gemm_u<1,2>, cudaFuncAttributeMaxDynamicSharedMemorySize, kSmemTotal);
    cudaFuncSetAttribute(gemm_u<2,3>, cudaFuncAttributeMaxDynamicSharedMemorySize, kSmemTotal);

    preconvert_w<<<dim3(20, 16), 256>>>(wq, wk, wvw, wl1, wl2);

    const size_t bufElems = (size_t)kN * kD;
    const dim3 gg(kD / 128, kN / 128);  // (2, 512)

    auto W = [&](int slot, int head) {
        return wimg + (size_t)(slot * 4 + head) * 262144;
    };

    const float *qin = in_q, *kin = in_k, *vin = in_v;
    for (int i = 0; i < kH; i++) {
        float* qout = bq + (size_t)(i & 1) * bufElems;
        float* kout = bk + (size_t)(i & 1) * bufElems;
        float* vout = bv + (size_t)(i & 1) * bufElems;

        zero_kernel<<<32, 256>>>(s1a, s2a, s1b, s2b, se, wv);

        gemm_u<0,0><<<gg, 256, kSmemTotal>>>(qin, nullptr, nullptr, nullptr,
            W(0,i), bqv + i*kD, qout, nullptr, nullptr, nullptr);
        gemm_u<0,0><<<gg, 256, kSmemTotal>>>(vin, nullptr, nullptr, nullptr,
            W(2,i), bvv + i*kD, vout, nullptr, nullptr, nullptr);
        // k projection + fused BN1 stats of (k' - q')
        gemm_u<0,1><<<gg, 256, kSmemTotal>>>(kin, nullptr, nullptr, nullptr,
            W(1,i), bkv + i*kD, kout, qout, s1a, s2a);

        bn_finalize_kernel<<<1, 256>>>(s1a, s2a, g1 + i*kD, be1 + i*kD, scA, shA);

        // linear1 on relu(bn(k'-q')) + fused BN2 stats
        gemm_u<1,2><<<gg, 256, kSmemTotal>>>(kout, qout, scA, shA,
            W(3,i), bl1 + i*kD, t2, nullptr, s1b, s2b);

        bn_finalize_kernel<<<1, 256>>>(s1b, s2b, g2 + i*kD, be2 + i*kD, scB, shB);

        // linear2 + fused softmax accumulation against v'
        gemm_u<2,3><<<gg, 256, kSmemTotal>>>(t2, nullptr, scB, shB,
            W(4,i), bl2 + i*kD, nullptr, vout, se, wv);

        softmax_final_kernel<<<kB, 256>>>(se, wv, concat, i);

        qin = qout; kin = kout; vin = vout;
    }

    mlp_kernel<<<kB, 256>>>(concat, mw0, mb0, mw1, mb1, mw2, mb2, (float*)d_out);
}